// round 1
// baseline (speedup 1.0000x reference)
#include <cuda_runtime.h>
#include <math.h>

#define DIMX 1024
#define INNER 1024
#define HEADS 16
#define HD 64
#define BATCH 2
#define NQ 2048
#define NM 2048
#define ROWS (BATCH * NQ)   // 4096

// ---------------- scratch (static device globals; no allocation allowed) ----
__device__ float g_kv[(size_t)BATCH * NM * 2 * INNER];  // [b*m, 2048] (k | v)
__device__ float g_q[(size_t)ROWS * INNER];             // [b*n, 1024]
__device__ float g_attn[(size_t)ROWS * INNER];          // attention out, [b,n,h*d]
__device__ float g_h1[(size_t)ROWS * DIMX];             // relu(attn @ w_out1)
__device__ float g_o2[(size_t)ROWS * DIMX];             // h1 @ w_out2 (pre-LN)

// ---------------- generic fp32 SGEMM: C[M,N] = A[M,K] @ B[K,N] --------------
// 128x128 block tile, 256 threads, 8x8 per-thread tile, K-step 8.
template <bool RELU>
__global__ __launch_bounds__(256) void sgemm128(const float* __restrict__ A,
                                                const float* __restrict__ B,
                                                float* __restrict__ C,
                                                int M, int N, int K) {
    __shared__ float As[8][132];   // A tile transposed: As[k][row]
    __shared__ float Bs[8][132];   // B tile natural:    Bs[k][col]

    const int tid = threadIdx.x;
    const int tx = tid & 15;       // 16 col groups
    const int ty = tid >> 4;       // 16 row groups
    const int brow = blockIdx.y * 128;
    const int bcol = blockIdx.x * 128;

    const int a_row = tid >> 1;          // 0..127
    const int a_col = (tid & 1) * 4;     // 0 or 4
    const int b_row = tid >> 5;          // 0..7
    const int b_col = (tid & 31) * 4;    // 0..124

    float acc[8][8];
#pragma unroll
    for (int i = 0; i < 8; i++)
#pragma unroll
        for (int j = 0; j < 8; j++) acc[i][j] = 0.f;

    const float* Ap = A + (size_t)(brow + a_row) * K + a_col;
    const float* Bp = B + (size_t)b_row * N + bcol + b_col;

    for (int k0 = 0; k0 < K; k0 += 8) {
        float4 av = *(const float4*)(Ap + k0);
        float4 bv = *(const float4*)(Bp + (size_t)k0 * N);
        As[a_col + 0][a_row] = av.x;
        As[a_col + 1][a_row] = av.y;
        As[a_col + 2][a_row] = av.z;
        As[a_col + 3][a_row] = av.w;
        *(float4*)&Bs[b_row][b_col] = bv;
        __syncthreads();
#pragma unroll
        for (int k = 0; k < 8; ++k) {
            float a[8], b[8];
            *(float4*)&a[0] = *(const float4*)&As[k][ty * 8];
            *(float4*)&a[4] = *(const float4*)&As[k][ty * 8 + 4];
            *(float4*)&b[0] = *(const float4*)&Bs[k][tx * 8];
            *(float4*)&b[4] = *(const float4*)&Bs[k][tx * 8 + 4];
#pragma unroll
            for (int i = 0; i < 8; i++)
#pragma unroll
                for (int j = 0; j < 8; j++) acc[i][j] = fmaf(a[i], b[j], acc[i][j]);
        }
        __syncthreads();
    }

#pragma unroll
    for (int i = 0; i < 8; i++) {
        float* crow = C + (size_t)(brow + ty * 8 + i) * N + bcol + tx * 8;
        float4 r0, r1;
        r0.x = acc[i][0]; r0.y = acc[i][1]; r0.z = acc[i][2]; r0.w = acc[i][3];
        r1.x = acc[i][4]; r1.y = acc[i][5]; r1.z = acc[i][6]; r1.w = acc[i][7];
        if (RELU) {
            r0.x = fmaxf(r0.x, 0.f); r0.y = fmaxf(r0.y, 0.f);
            r0.z = fmaxf(r0.z, 0.f); r0.w = fmaxf(r0.w, 0.f);
            r1.x = fmaxf(r1.x, 0.f); r1.y = fmaxf(r1.y, 0.f);
            r1.z = fmaxf(r1.z, 0.f); r1.w = fmaxf(r1.w, 0.f);
        }
        *(float4*)crow = r0;
        *(float4*)(crow + 4) = r1;
    }
}

// ---------------- flash attention (fp32, online softmax) --------------------
// grid: (n/64, HEADS, BATCH); 256 threads; 64 query rows x 64-key tiles, d=64.
// SMEM: Qs^T [d][row], KP (K^T [d][key], then P^T [key][row]), Vs [key][d].
#define FA_PAD 68
__global__ __launch_bounds__(256) void flash_kernel(const float* __restrict__ Q,
                                                    const float* __restrict__ KV,
                                                    float* __restrict__ O) {
    extern __shared__ float sm[];
    float* Qs = sm;                       // 64*68
    float* KP = sm + 64 * FA_PAD;         // 64*68
    float* Vs = sm + 2 * 64 * FA_PAD;     // 64*68

    const int tid = threadIdx.x;
    const int tx = tid & 15;
    const int ty = tid >> 4;
    const int n0 = blockIdx.x * 64;
    const int h = blockIdx.y;
    const int b = blockIdx.z;

    const float* qg = Q + (size_t)(b * NQ + n0) * INNER + h * HD;
    for (int i = tid; i < 64 * 16; i += 256) {
        int r = i >> 4;
        int dg = (i & 15) * 4;
        float4 v = *(const float4*)(qg + (size_t)r * INNER + dg);
        Qs[(dg + 0) * FA_PAD + r] = v.x;
        Qs[(dg + 1) * FA_PAD + r] = v.y;
        Qs[(dg + 2) * FA_PAD + r] = v.z;
        Qs[(dg + 3) * FA_PAD + r] = v.w;
    }

    float m_i[4], l_i[4], acc[4][4];
#pragma unroll
    for (int i = 0; i < 4; i++) {
        m_i[i] = -1e30f;
        l_i[i] = 0.f;
#pragma unroll
        for (int j = 0; j < 4; j++) acc[i][j] = 0.f;
    }

    const float* kg = KV + (size_t)b * NM * (2 * INNER) + h * HD;
    const float scale = 0.125f;  // 1/sqrt(64)

    for (int jt = 0; jt < NM / 64; jt++) {
        __syncthreads();  // previous tile's KP/Vs reads complete
        const float* kt = kg + (size_t)jt * 64 * (2 * INNER);
        for (int i = tid; i < 64 * 16; i += 256) {
            int r = i >> 4;
            int dg = (i & 15) * 4;
            float4 kvv = *(const float4*)(kt + (size_t)r * (2 * INNER) + dg);
            KP[(dg + 0) * FA_PAD + r] = kvv.x;
            KP[(dg + 1) * FA_PAD + r] = kvv.y;
            KP[(dg + 2) * FA_PAD + r] = kvv.z;
            KP[(dg + 3) * FA_PAD + r] = kvv.w;
            float4 vv = *(const float4*)(kt + (size_t)r * (2 * INNER) + INNER + dg);
            *(float4*)&Vs[r * FA_PAD + dg] = vv;
        }
        __syncthreads();

        // S = Q @ K^T  (each thread: 4 rows x 4 key-cols)
        float s[4][4];
#pragma unroll
        for (int i = 0; i < 4; i++)
#pragma unroll
            for (int j = 0; j < 4; j++) s[i][j] = 0.f;
#pragma unroll 8
        for (int d = 0; d < 64; d++) {
            float4 qa = *(const float4*)&Qs[d * FA_PAD + ty * 4];
            float4 kb = *(const float4*)&KP[d * FA_PAD + tx * 4];
            float qv[4] = {qa.x, qa.y, qa.z, qa.w};
            float kv_[4] = {kb.x, kb.y, kb.z, kb.w};
#pragma unroll
            for (int i = 0; i < 4; i++)
#pragma unroll
                for (int j = 0; j < 4; j++) s[i][j] = fmaf(qv[i], kv_[j], s[i][j]);
        }

        // online softmax per row (16 lanes own a row's 64 cols; lanes contiguous
        // within half-warps, so shfl_xor over {1,2,4,8} stays in-group)
#pragma unroll
        for (int i = 0; i < 4; i++) {
            float rm = -1e30f;
#pragma unroll
            for (int j = 0; j < 4; j++) {
                s[i][j] *= scale;
                rm = fmaxf(rm, s[i][j]);
            }
#pragma unroll
            for (int o = 8; o >= 1; o >>= 1)
                rm = fmaxf(rm, __shfl_xor_sync(0xffffffffu, rm, o));
            float mn = fmaxf(m_i[i], rm);
            float corr = __expf(m_i[i] - mn);
            m_i[i] = mn;
            float rs = 0.f;
#pragma unroll
            for (int j = 0; j < 4; j++) {
                s[i][j] = __expf(s[i][j] - mn);
                rs += s[i][j];
            }
#pragma unroll
            for (int o = 8; o >= 1; o >>= 1) rs += __shfl_xor_sync(0xffffffffu, rs, o);
            l_i[i] = l_i[i] * corr + rs;
#pragma unroll
            for (int j = 0; j < 4; j++) acc[i][j] *= corr;
        }

        __syncthreads();  // done reading K from KP
        // store P transposed: KP[key][row]
#pragma unroll
        for (int j = 0; j < 4; j++) {
            float4 pc;
            pc.x = s[0][j]; pc.y = s[1][j]; pc.z = s[2][j]; pc.w = s[3][j];
            *(float4*)&KP[(tx * 4 + j) * FA_PAD + ty * 4] = pc;
        }
        __syncthreads();

        // O += P @ V
#pragma unroll 8
        for (int key = 0; key < 64; key++) {
            float4 pa = *(const float4*)&KP[key * FA_PAD + ty * 4];
            float4 vb = *(const float4*)&Vs[key * FA_PAD + tx * 4];
            float pv[4] = {pa.x, pa.y, pa.z, pa.w};
            float vv[4] = {vb.x, vb.y, vb.z, vb.w};
#pragma unroll
            for (int i = 0; i < 4; i++)
#pragma unroll
                for (int j = 0; j < 4; j++) acc[i][j] = fmaf(pv[i], vv[j], acc[i][j]);
        }
    }

    float* og = O + (size_t)(b * NQ + n0) * INNER + h * HD;
#pragma unroll
    for (int i = 0; i < 4; i++) {
        float inv = 1.f / l_i[i];
        float4 r;
        r.x = acc[i][0] * inv; r.y = acc[i][1] * inv;
        r.z = acc[i][2] * inv; r.w = acc[i][3] * inv;
        *(float4*)(og + (size_t)(ty * 4 + i) * INNER + tx * 4) = r;
    }
}

// ---------------- layernorm over last dim (1024), gamma, beta=0 -------------
__global__ __launch_bounds__(256) void ln_kernel(const float* __restrict__ X,
                                                 const float* __restrict__ gamma,
                                                 float* __restrict__ out) {
    const int row = blockIdx.x;
    const int tid = threadIdx.x;
    const float* xr = X + (size_t)row * DIMX;
    float4 v = *(const float4*)(xr + tid * 4);
    float s = v.x + v.y + v.z + v.w;
    float ss = v.x * v.x + v.y * v.y + v.z * v.z + v.w * v.w;
#pragma unroll
    for (int o = 16; o >= 1; o >>= 1) {
        s += __shfl_xor_sync(0xffffffffu, s, o);
        ss += __shfl_xor_sync(0xffffffffu, ss, o);
    }
    __shared__ float rs[8], rss[8];
    __shared__ float mean_s, rstd_s;
    const int warp = tid >> 5;
    if ((tid & 31) == 0) { rs[warp] = s; rss[warp] = ss; }
    __syncthreads();
    if (tid == 0) {
        float ts = 0.f, tss = 0.f;
#pragma unroll
        for (int w = 0; w < 8; w++) { ts += rs[w]; tss += rss[w]; }
        float mean = ts * (1.0f / DIMX);
        float var = tss * (1.0f / DIMX) - mean * mean;
        mean_s = mean;
        rstd_s = rsqrtf(var + 1e-5f);
    }
    __syncthreads();
    float mean = mean_s, rstd = rstd_s;
    float4 g = *(const float4*)(gamma + tid * 4);
    float4 r;
    r.x = (v.x - mean) * rstd * g.x;
    r.y = (v.y - mean) * rstd * g.y;
    r.z = (v.z - mean) * rstd * g.z;
    r.w = (v.w - mean) * rstd * g.w;
    *(float4*)(out + (size_t)row * DIMX + tid * 4) = r;
}

// ---------------- launch ----------------------------------------------------
extern "C" void kernel_launch(void* const* d_in, const int* in_sizes, int n_in,
                              void* d_out, int out_size) {
    const float* x       = (const float*)d_in[0];
    const float* context = (const float*)d_in[1];
    const float* w_kv    = (const float*)d_in[2];
    const float* w_q     = (const float*)d_in[3];
    const float* w_out1  = (const float*)d_in[4];
    const float* w_out2  = (const float*)d_in[5];
    const float* gamma   = (const float*)d_in[6];
    float* out = (float*)d_out;

    void *p_kv, *p_q, *p_attn, *p_h1, *p_o2;
    cudaGetSymbolAddress(&p_kv, g_kv);
    cudaGetSymbolAddress(&p_q, g_q);
    cudaGetSymbolAddress(&p_attn, g_attn);
    cudaGetSymbolAddress(&p_h1, g_h1);
    cudaGetSymbolAddress(&p_o2, g_o2);

    const int FA_SMEM = 3 * 64 * FA_PAD * (int)sizeof(float);  // 52224 B
    cudaFuncSetAttribute(flash_kernel, cudaFuncAttributeMaxDynamicSharedMemorySize,
                         FA_SMEM);

    // kv = context @ w_kv   [4096,1024]x[1024,2048]
    sgemm128<false><<<dim3(2048 / 128, ROWS / 128), 256>>>(
        context, w_kv, (float*)p_kv, ROWS, 2 * INNER, DIMX);
    // q = x @ w_q           [4096,1024]x[1024,1024]
    sgemm128<false><<<dim3(INNER / 128, ROWS / 128), 256>>>(
        x, w_q, (float*)p_q, ROWS, INNER, DIMX);
    // attention
    flash_kernel<<<dim3(NQ / 64, HEADS, BATCH), 256, FA_SMEM>>>(
        (const float*)p_q, (const float*)p_kv, (float*)p_attn);
    // h1 = relu(attn @ w_out1)
    sgemm128<true><<<dim3(DIMX / 128, ROWS / 128), 256>>>(
        (const float*)p_attn, w_out1, (float*)p_h1, ROWS, DIMX, INNER);
    // o2 = h1 @ w_out2
    sgemm128<false><<<dim3(DIMX / 128, ROWS / 128), 256>>>(
        (const float*)p_h1, w_out2, (float*)p_o2, ROWS, DIMX, DIMX);
    // layernorm -> d_out
    ln_kernel<<<ROWS, 256>>>((const float*)p_o2, gamma, out);
}

// round 5
// speedup vs baseline: 2.4552x; 2.4552x over previous
#include <cuda_runtime.h>
#include <cuda_bf16.h>
#include <math.h>
#include <stdint.h>

#define DIMX 1024
#define INNER 1024
#define HEADS 16
#define HD 64
#define BATCH 2
#define NQ 2048
#define NM 2048
#define ROWS (BATCH * NQ)   // 4096

typedef __nv_bfloat16 bf16;

// ---------------- scratch (static device globals) ---------------------------
__device__ bf16 g_xh[(size_t)ROWS * DIMX],  g_xl[(size_t)ROWS * DIMX];
__device__ bf16 g_ch[(size_t)ROWS * DIMX],  g_cl[(size_t)ROWS * DIMX];
__device__ bf16 g_kh[(size_t)ROWS * INNER], g_kl[(size_t)ROWS * INNER];
__device__ bf16 g_vTh[(size_t)BATCH * HEADS * HD * NM];
__device__ bf16 g_vTl[(size_t)BATCH * HEADS * HD * NM];
__device__ bf16 g_qh[(size_t)ROWS * INNER], g_ql[(size_t)ROWS * INNER];
__device__ bf16 g_ah[(size_t)ROWS * INNER], g_al[(size_t)ROWS * INNER];
__device__ bf16 g_h1h[(size_t)ROWS * DIMX], g_h1l[(size_t)ROWS * DIMX];
__device__ float g_o2[(size_t)ROWS * DIMX];
__device__ bf16 g_wkvTh[(size_t)2 * INNER * DIMX], g_wkvTl[(size_t)2 * INNER * DIMX];
__device__ bf16 g_wqTh[(size_t)INNER * DIMX],  g_wqTl[(size_t)INNER * DIMX];
__device__ bf16 g_w1Th[(size_t)DIMX * INNER],  g_w1Tl[(size_t)DIMX * INNER];
__device__ bf16 g_w2Th[(size_t)DIMX * DIMX],   g_w2Tl[(size_t)DIMX * DIMX];

// ---------------- PTX helpers (sm_80-level only) ----------------------------
__device__ __forceinline__ uint32_t smem_u32(const void* p) {
    uint32_t a;
    asm("{ .reg .u64 t; cvta.to.shared.u64 t, %1; cvt.u32.u64 %0, t; }"
        : "=r"(a) : "l"(p));
    return a;
}
__device__ __forceinline__ void cp16(uint32_t dst, const void* src) {
    asm volatile("cp.async.cg.shared.global [%0], [%1], 16;" :: "r"(dst), "l"(src));
}
__device__ __forceinline__ void cp_commit() {
    asm volatile("cp.async.commit_group;" ::: "memory");
}
template <int N>
__device__ __forceinline__ void cp_wait() {
    asm volatile("cp.async.wait_group %0;" :: "n"(N) : "memory");
}
__device__ __forceinline__ void ldsm4(uint32_t (&r)[4], uint32_t addr) {
    asm volatile("ldmatrix.sync.aligned.m8n8.x4.shared.b16 {%0,%1,%2,%3}, [%4];"
        : "=r"(r[0]), "=r"(r[1]), "=r"(r[2]), "=r"(r[3]) : "r"(addr));
}
// A fragment (m16k16): matrices {rows0-7,k0-7},{rows8-15,k0-7},{rows0-7,k8-15},{rows8-15,k8-15}
__device__ __forceinline__ void ldsmA4(uint32_t (&r)[4], uint32_t base, int strideB,
                                       int row0, int col) {
    int lane = threadIdx.x & 31, m = lane >> 3, rr = lane & 7;
    ldsm4(r, base + (row0 + ((m & 1) << 3) + rr) * strideB + (col + ((m >> 1) << 3)) * 2);
}
// B fragments for 2 n8-tiles (n16 group): {n0-7,k0-7},{n0-7,k8-15},{n8-15,k0-7},{n8-15,k8-15}
__device__ __forceinline__ void ldsmB4(uint32_t (&r)[4], uint32_t base, int strideB,
                                       int nrow0, int col) {
    int lane = threadIdx.x & 31, m = lane >> 3, rr = lane & 7;
    ldsm4(r, base + (nrow0 + ((m >> 1) << 3) + rr) * strideB + (col + ((m & 1) << 3)) * 2);
}
__device__ __forceinline__ void mma16(float (&d)[4], const uint32_t (&a)[4],
                                      uint32_t b0, uint32_t b1) {
    asm volatile("mma.sync.aligned.m16n8k16.row.col.f32.bf16.bf16.f32 "
        "{%0,%1,%2,%3}, {%4,%5,%6,%7}, {%8,%9}, {%0,%1,%2,%3};"
        : "+f"(d[0]), "+f"(d[1]), "+f"(d[2]), "+f"(d[3])
        : "r"(a[0]), "r"(a[1]), "r"(a[2]), "r"(a[3]), "r"(b0), "r"(b1));
}
__device__ __forceinline__ uint32_t pack_bf(float lo, float hi) {
    __nv_bfloat162 t = __floats2bfloat162_rn(lo, hi);
    return *(uint32_t*)&t;
}
__device__ __forceinline__ float bfres(float x) {
    return x - __bfloat162float(__float2bfloat16_rn(x));
}

// ======================= bf16x3 GEMM ========================================
// C[M,N] = A[M,K] @ Bt^T. A/Bt given as bf16 hi/lo planes, [rows][K].
#define TM 128
#define TN 128
#define KT 32
#define GST 80                       // smem row stride bytes (32 bf16 + pad)
#define PL (TM * GST)                // 10240 bytes per plane
#define STGB (4 * PL)                // AH AL BH BL
#define GSMEM (3 * STGB)             // 122880

// MODE: 0 fp32 C; 1 relu -> Ch/Cl; 2 kv split; 3 -> Ch/Cl
template <int MODE>
__global__ __launch_bounds__(256, 1) void gemm_b3(const bf16* __restrict__ Ah,
                                                  const bf16* __restrict__ Al,
                                                  const bf16* __restrict__ Bh,
                                                  const bf16* __restrict__ Bl,
                                                  float* __restrict__ C,
                                                  bf16* __restrict__ Ch,
                                                  bf16* __restrict__ Cl,
                                                  bf16* __restrict__ C2h,
                                                  bf16* __restrict__ C2l,
                                                  int K, int ldc) {
    extern __shared__ __align__(128) char smem[];
    const uint32_t sb = smem_u32(smem);
    const int tid = threadIdx.x, lane = tid & 31, wid = tid >> 5;
    const int brow = blockIdx.y * TM, bcol = blockIdx.x * TN;
    const int m0 = (wid >> 2) * 64, n0 = (wid & 3) * 32;

    float acc[4][4][4];
#pragma unroll
    for (int i = 0; i < 4; i++)
#pragma unroll
        for (int j = 0; j < 4; j++)
#pragma unroll
            for (int c = 0; c < 4; c++) acc[i][j][c] = 0.f;

    auto load_stage = [&](int buf, int k0) {
        uint32_t s0 = sb + buf * STGB;
        const bf16* srcs[4] = {Ah, Al, Bh, Bl};
        const int r0s[4] = {brow, brow, bcol, bcol};
#pragma unroll
        for (int p = 0; p < 4; p++) {
            uint32_t pb = s0 + p * PL;
#pragma unroll
            for (int i = 0; i < 2; i++) {
                int idx = tid + i * 256, r = idx >> 2, c = idx & 3;
                cp16(pb + r * GST + c * 16,
                     srcs[p] + (size_t)(r0s[p] + r) * K + k0 + c * 8);
            }
        }
        cp_commit();
    };

    const int NK = K / KT;
    load_stage(0, 0);
    load_stage(1, KT);
    load_stage(2, 2 * KT);

    for (int ks = 0; ks < NK; ks++) {
        int rem = NK - 1 - ks;
        if (rem >= 2)      cp_wait<2>();
        else if (rem == 1) cp_wait<1>();
        else               cp_wait<0>();
        __syncthreads();
        uint32_t s0 = sb + (ks % 3) * STGB;
#pragma unroll
        for (int k16 = 0; k16 < 2; k16++) {
            int kc = k16 * 16;
            uint32_t aH[4][4], aL[4][4];
#pragma unroll
            for (int mt = 0; mt < 4; mt++) {
                ldsmA4(aH[mt], s0, GST, m0 + mt * 16, kc);
                ldsmA4(aL[mt], s0 + PL, GST, m0 + mt * 16, kc);
            }
#pragma unroll
            for (int g = 0; g < 2; g++) {
                uint32_t bH[4], bL[4];
                ldsmB4(bH, s0 + 2 * PL, GST, n0 + g * 16, kc);
                ldsmB4(bL, s0 + 3 * PL, GST, n0 + g * 16, kc);
#pragma unroll
                for (int mt = 0; mt < 4; mt++) {
                    mma16(acc[mt][2 * g], aH[mt], bH[0], bH[1]);
                    mma16(acc[mt][2 * g], aH[mt], bL[0], bL[1]);
                    mma16(acc[mt][2 * g], aL[mt], bH[0], bH[1]);
                    mma16(acc[mt][2 * g + 1], aH[mt], bH[2], bH[3]);
                    mma16(acc[mt][2 * g + 1], aH[mt], bL[2], bL[3]);
                    mma16(acc[mt][2 * g + 1], aL[mt], bH[2], bH[3]);
                }
            }
        }
        __syncthreads();
        if (ks + 3 < NK) load_stage(ks % 3, (ks + 3) * KT);
    }

#pragma unroll
    for (int mt = 0; mt < 4; mt++)
#pragma unroll
        for (int nt = 0; nt < 4; nt++) {
            int rg = brow + m0 + mt * 16 + (lane >> 2);
            int cg = bcol + n0 + nt * 8 + 2 * (lane & 3);
            float c0 = acc[mt][nt][0], c1 = acc[mt][nt][1];
            float c2 = acc[mt][nt][2], c3 = acc[mt][nt][3];
            if (MODE == 1) {
                c0 = fmaxf(c0, 0.f); c1 = fmaxf(c1, 0.f);
                c2 = fmaxf(c2, 0.f); c3 = fmaxf(c3, 0.f);
            }
            if (MODE == 0) {
                *(float2*)(C + (size_t)rg * ldc + cg) = make_float2(c0, c1);
                *(float2*)(C + (size_t)(rg + 8) * ldc + cg) = make_float2(c2, c3);
            } else if (MODE == 2 && cg >= 1024) {
                int df = cg - 1024, h = df >> 6, d = df & 63;
                int b2 = rg >> 11, m = rg & 2047;
                size_t i0 = ((size_t)((b2 * HEADS + h) * HD) + d) * NM + m;
                size_t i1 = i0 + NM;  // d+1
                C2h[i0] = __float2bfloat16_rn(c0); C2l[i0] = __float2bfloat16_rn(bfres(c0));
                C2h[i1] = __float2bfloat16_rn(c1); C2l[i1] = __float2bfloat16_rn(bfres(c1));
                C2h[i0 + 8] = __float2bfloat16_rn(c2); C2l[i0 + 8] = __float2bfloat16_rn(bfres(c2));
                C2h[i1 + 8] = __float2bfloat16_rn(c3); C2l[i1 + 8] = __float2bfloat16_rn(bfres(c3));
            } else {
                uint32_t h01 = pack_bf(c0, c1), l01 = pack_bf(bfres(c0), bfres(c1));
                uint32_t h23 = pack_bf(c2, c3), l23 = pack_bf(bfres(c2), bfres(c3));
                *(uint32_t*)(Ch + (size_t)rg * ldc + cg) = h01;
                *(uint32_t*)(Cl + (size_t)rg * ldc + cg) = l01;
                *(uint32_t*)(Ch + (size_t)(rg + 8) * ldc + cg) = h23;
                *(uint32_t*)(Cl + (size_t)(rg + 8) * ldc + cg) = l23;
            }
        }
}

// ======================= bf16x3 flash attention =============================
#define AST 144                      // smem row stride bytes (64 bf16 + pad)
#define OFF_QH 0
#define OFF_QL (128 * AST)           // 18432
#define OFF_BUF (2 * 128 * AST)      // 36864
#define BUF_SZ (4 * 64 * AST)        // KH KL VH VL, 36864
#define B_KH 0
#define B_KL (64 * AST)
#define B_VH (2 * 64 * AST)
#define B_VL (3 * 64 * AST)
#define ATT_SMEM (OFF_BUF + 2 * BUF_SZ)  // 110592

__global__ __launch_bounds__(256, 1) void attn_b3(const bf16* __restrict__ Qh,
                                                  const bf16* __restrict__ Ql,
                                                  const bf16* __restrict__ Kh,
                                                  const bf16* __restrict__ Kl,
                                                  const bf16* __restrict__ Vh,
                                                  const bf16* __restrict__ Vl,
                                                  bf16* __restrict__ Oh,
                                                  bf16* __restrict__ Ol) {
    extern __shared__ __align__(128) char smem[];
    const uint32_t sb = smem_u32(smem);
    const int tid = threadIdx.x, lane = tid & 31, wid = tid >> 5;
    const int qt = blockIdx.x, h = blockIdx.y, b = blockIdx.z;

    const size_t qrow0 = (size_t)(b * NQ + qt * 128);
    const bf16* qh = Qh + qrow0 * INNER + h * HD;
    const bf16* ql = Ql + qrow0 * INNER + h * HD;
    const bf16* kh = Kh + (size_t)(b * NM) * INNER + h * HD;
    const bf16* kl = Kl + (size_t)(b * NM) * INNER + h * HD;
    const bf16* vh = Vh + (size_t)((b * HEADS + h) * HD) * NM;
    const bf16* vl = Vl + (size_t)((b * HEADS + h) * HD) * NM;

    // Q hi/lo -> smem (goes into first commit group)
#pragma unroll
    for (int i = 0; i < 4; i++) {
        int idx = tid + i * 256, r = idx >> 3, c = idx & 7;
        cp16(sb + OFF_QH + r * AST + c * 16, qh + (size_t)r * INNER + c * 8);
        cp16(sb + OFF_QL + r * AST + c * 16, ql + (size_t)r * INNER + c * 8);
    }
    auto load_kv = [&](int buf, int j) {
        uint32_t bb = sb + OFF_BUF + buf * BUF_SZ;
#pragma unroll
        for (int i = 0; i < 2; i++) {
            int idx = tid + i * 256, r = idx >> 3, c = idx & 7;
            cp16(bb + B_KH + r * AST + c * 16, kh + (size_t)(j * 64 + r) * INNER + c * 8);
            cp16(bb + B_KL + r * AST + c * 16, kl + (size_t)(j * 64 + r) * INNER + c * 8);
            cp16(bb + B_VH + r * AST + c * 16, vh + (size_t)r * NM + j * 64 + c * 8);
            cp16(bb + B_VL + r * AST + c * 16, vl + (size_t)r * NM + j * 64 + c * 8);
        }
        cp_commit();
    };
    load_kv(0, 0);

    const int q0 = wid * 16;
    float Oacc[8][4];
#pragma unroll
    for (int i = 0; i < 8; i++)
#pragma unroll
        for (int c = 0; c < 4; c++) Oacc[i][c] = 0.f;
    float m_lo = -1e30f, m_hi = -1e30f, l_lo = 0.f, l_hi = 0.f;

    for (int j = 0; j < NM / 64; j++) {
        const int buf = j & 1;
        if (j + 1 < NM / 64) { load_kv(buf ^ 1, j + 1); cp_wait<1>(); }
        else                 { cp_wait<0>(); }
        __syncthreads();
        uint32_t bb = sb + OFF_BUF + buf * BUF_SZ;

        // S = Q @ K^T  (k-dim = d = 64)
        float S[8][4];
#pragma unroll
        for (int i = 0; i < 8; i++)
#pragma unroll
            for (int c = 0; c < 4; c++) S[i][c] = 0.f;
#pragma unroll
        for (int s = 0; s < 4; s++) {
            int kc = s * 16;
            uint32_t aH[4], aL[4];
            ldsmA4(aH, sb + OFF_QH, AST, q0, kc);
            ldsmA4(aL, sb + OFF_QL, AST, q0, kc);
#pragma unroll
            for (int g = 0; g < 4; g++) {
                uint32_t bH[4], bL[4];
                ldsmB4(bH, bb + B_KH, AST, g * 16, kc);
                ldsmB4(bL, bb + B_KL, AST, g * 16, kc);
                mma16(S[2 * g], aH, bH[0], bH[1]);
                mma16(S[2 * g], aH, bL[0], bL[1]);
                mma16(S[2 * g], aL, bH[0], bH[1]);
                mma16(S[2 * g + 1], aH, bH[2], bH[3]);
                mma16(S[2 * g + 1], aH, bL[2], bL[3]);
                mma16(S[2 * g + 1], aL, bH[2], bH[3]);
            }
        }

        // online softmax
        float tm_lo = -1e30f, tm_hi = -1e30f;
#pragma unroll
        for (int nt = 0; nt < 8; nt++) {
#pragma unroll
            for (int c = 0; c < 4; c++) S[nt][c] *= 0.125f;
            tm_lo = fmaxf(tm_lo, fmaxf(S[nt][0], S[nt][1]));
            tm_hi = fmaxf(tm_hi, fmaxf(S[nt][2], S[nt][3]));
        }
        tm_lo = fmaxf(tm_lo, __shfl_xor_sync(0xffffffffu, tm_lo, 1));
        tm_lo = fmaxf(tm_lo, __shfl_xor_sync(0xffffffffu, tm_lo, 2));
        tm_hi = fmaxf(tm_hi, __shfl_xor_sync(0xffffffffu, tm_hi, 1));
        tm_hi = fmaxf(tm_hi, __shfl_xor_sync(0xffffffffu, tm_hi, 2));
        float mn_lo = fmaxf(m_lo, tm_lo), mn_hi = fmaxf(m_hi, tm_hi);
        float corr_lo = __expf(m_lo - mn_lo), corr_hi = __expf(m_hi - mn_hi);
        m_lo = mn_lo; m_hi = mn_hi;
        float s_lo = 0.f, s_hi = 0.f;
#pragma unroll
        for (int nt = 0; nt < 8; nt++) {
            S[nt][0] = __expf(S[nt][0] - mn_lo);
            S[nt][1] = __expf(S[nt][1] - mn_lo);
            S[nt][2] = __expf(S[nt][2] - mn_hi);
            S[nt][3] = __expf(S[nt][3] - mn_hi);
            s_lo += S[nt][0] + S[nt][1];
            s_hi += S[nt][2] + S[nt][3];
        }
        s_lo += __shfl_xor_sync(0xffffffffu, s_lo, 1);
        s_lo += __shfl_xor_sync(0xffffffffu, s_lo, 2);
        s_hi += __shfl_xor_sync(0xffffffffu, s_hi, 1);
        s_hi += __shfl_xor_sync(0xffffffffu, s_hi, 2);
        l_lo = l_lo * corr_lo + s_lo;
        l_hi = l_hi * corr_hi + s_hi;
#pragma unroll
        for (int nt = 0; nt < 8; nt++) {
            Oacc[nt][0] *= corr_lo; Oacc[nt][1] *= corr_lo;
            Oacc[nt][2] *= corr_hi; Oacc[nt][3] *= corr_hi;
        }

        // P fragments directly from S registers (acc layout == A-frag layout)
        uint32_t pH[4][4], pL[4][4];
#pragma unroll
        for (int t = 0; t < 4; t++) {
            pH[t][0] = pack_bf(S[2 * t][0], S[2 * t][1]);
            pH[t][1] = pack_bf(S[2 * t][2], S[2 * t][3]);
            pH[t][2] = pack_bf(S[2 * t + 1][0], S[2 * t + 1][1]);
            pH[t][3] = pack_bf(S[2 * t + 1][2], S[2 * t + 1][3]);
            pL[t][0] = pack_bf(bfres(S[2 * t][0]), bfres(S[2 * t][1]));
            pL[t][1] = pack_bf(bfres(S[2 * t][2]), bfres(S[2 * t][3]));
            pL[t][2] = pack_bf(bfres(S[2 * t + 1][0]), bfres(S[2 * t + 1][1]));
            pL[t][3] = pack_bf(bfres(S[2 * t + 1][2]), bfres(S[2 * t + 1][3]));
        }

        // O += P @ V  (k-dim = keys = 64; V^T smem rows = d)
#pragma unroll
        for (int t = 0; t < 4; t++) {
            int kc = t * 16;
#pragma unroll
            for (int g = 0; g < 4; g++) {
                uint32_t bH[4], bL[4];
                ldsmB4(bH, bb + B_VH, AST, g * 16, kc);
                ldsmB4(bL, bb + B_VL, AST, g * 16, kc);
                mma16(Oacc[2 * g], pH[t], bH[0], bH[1]);
                mma16(Oacc[2 * g], pH[t], bL[0], bL[1]);
                mma16(Oacc[2 * g], pL[t], bH[0], bH[1]);
                mma16(Oacc[2 * g + 1], pH[t], bH[2], bH[3]);
                mma16(Oacc[2 * g + 1], pH[t], bL[2], bL[3]);
                mma16(Oacc[2 * g + 1], pL[t], bH[2], bH[3]);
            }
        }
        __syncthreads();
    }

    float inv_lo = 1.f / l_lo, inv_hi = 1.f / l_hi;
    int r = q0 + (lane >> 2), c = 2 * (lane & 3);
    bf16* oh = Oh + (qrow0 + r) * INNER + h * HD;
    bf16* ol = Ol + (qrow0 + r) * INNER + h * HD;
#pragma unroll
    for (int nt = 0; nt < 8; nt++) {
        float c0 = Oacc[nt][0] * inv_lo, c1 = Oacc[nt][1] * inv_lo;
        float c2 = Oacc[nt][2] * inv_hi, c3 = Oacc[nt][3] * inv_hi;
        *(uint32_t*)(oh + nt * 8 + c) = pack_bf(c0, c1);
        *(uint32_t*)(ol + nt * 8 + c) = pack_bf(bfres(c0), bfres(c1));
        *(uint32_t*)(oh + 8 * INNER + nt * 8 + c) = pack_bf(c2, c3);
        *(uint32_t*)(ol + 8 * INNER + nt * 8 + c) = pack_bf(bfres(c2), bfres(c3));
    }
}

// ---------------- conversion / transpose kernels ----------------------------
__global__ __launch_bounds__(256) void conv_split(const float* __restrict__ in,
                                                  bf16* __restrict__ hi,
                                                  bf16* __restrict__ lo) {
    size_t i = ((size_t)blockIdx.x * 256 + threadIdx.x) * 4;
    float4 v = *(const float4*)(in + i);
    __nv_bfloat162 h0 = __floats2bfloat162_rn(v.x, v.y);
    __nv_bfloat162 h1 = __floats2bfloat162_rn(v.z, v.w);
    __nv_bfloat162 l0 = __floats2bfloat162_rn(v.x - __bfloat162float(h0.x),
                                              v.y - __bfloat162float(h0.y));
    __nv_bfloat162 l1 = __floats2bfloat162_rn(v.z - __bfloat162float(h1.x),
                                              v.w - __bfloat162float(h1.y));
    *(__nv_bfloat162*)(hi + i) = h0;
    *(__nv_bfloat162*)(hi + i + 2) = h1;
    *(__nv_bfloat162*)(lo + i) = l0;
    *(__nv_bfloat162*)(lo + i + 2) = l1;
}

__global__ __launch_bounds__(256) void transpose_conv(const float* __restrict__ in,
                                                      bf16* __restrict__ outh,
                                                      bf16* __restrict__ outl,
                                                      int K, int N) {
    __shared__ float t[32][33];
    int x = blockIdx.x * 32 + threadIdx.x;
    int y0 = blockIdx.y * 32 + threadIdx.y;
#pragma unroll
    for (int j = 0; j < 32; j += 8)
        t[threadIdx.y + j][threadIdx.x] = in[(size_t)(y0 + j) * N + x];
    __syncthreads();
    int x2 = blockIdx.y * 32 + threadIdx.x;
    int y2 = blockIdx.x * 32 + threadIdx.y;
#pragma unroll
    for (int j = 0; j < 32; j += 8) {
        float v = t[threadIdx.x][threadIdx.y + j];
        bf16 h = __float2bfloat16_rn(v);
        outh[(size_t)(y2 + j) * K + x2] = h;
        outl[(size_t)(y2 + j) * K + x2] = __float2bfloat16_rn(v - __bfloat162float(h));
    }
}

// ---------------- layernorm over last dim (1024) ----------------------------
__global__ __launch_bounds__(256) void ln_kernel(const float* __restrict__ X,
                                                 const float* __restrict__ gamma,
                                                 float* __restrict__ out) {
    const int row = blockIdx.x;
    const int tid = threadIdx.x;
    const float* xr = X + (size_t)row * DIMX;
    float4 v = *(const float4*)(xr + tid * 4);
    float s = v.x + v.y + v.z + v.w;
    float ss = v.x * v.x + v.y * v.y + v.z * v.z + v.w * v.w;
#pragma unroll
    for (int o = 16; o >= 1; o >>= 1) {
        s += __shfl_xor_sync(0xffffffffu, s, o);
        ss += __shfl_xor_sync(0xffffffffu, ss, o);
    }
    __shared__ float rs[8], rss[8];
    __shared__ float mean_s, rstd_s;
    const int warp = tid >> 5;
    if ((tid & 31) == 0) { rs[warp] = s; rss[warp] = ss; }
    __syncthreads();
    if (tid == 0) {
        float ts = 0.f, tss = 0.f;
#pragma unroll
        for (int w = 0; w < 8; w++) { ts += rs[w]; tss += rss[w]; }
        float mean = ts * (1.0f / DIMX);
        float var = tss * (1.0f / DIMX) - mean * mean;
        mean_s = mean;
        rstd_s = rsqrtf(var + 1e-5f);
    }
    __syncthreads();
    float mean = mean_s, rstd = rstd_s;
    float4 g = *(const float4*)(gamma + tid * 4);
    float4 r;
    r.x = (v.x - mean) * rstd * g.x;
    r.y = (v.y - mean) * rstd * g.y;
    r.z = (v.z - mean) * rstd * g.z;
    r.w = (v.w - mean) * rstd * g.w;
    *(float4*)(out + (size_t)row * DIMX + tid * 4) = r;
}

// ---------------- launch ----------------------------------------------------
#define SYM(p, s) void* p; cudaGetSymbolAddress(&p, s)

extern "C" void kernel_launch(void* const* d_in, const int* in_sizes, int n_in,
                              void* d_out, int out_size) {
    const float* x       = (const float*)d_in[0];
    const float* context = (const float*)d_in[1];
    const float* w_kv    = (const float*)d_in[2];
    const float* w_q     = (const float*)d_in[3];
    const float* w_out1  = (const float*)d_in[4];
    const float* w_out2  = (const float*)d_in[5];
    const float* gamma   = (const float*)d_in[6];
    float* out = (float*)d_out;

    SYM(p_xh, g_xh);   SYM(p_xl, g_xl);
    SYM(p_ch, g_ch);   SYM(p_cl, g_cl);
    SYM(p_kh, g_kh);   SYM(p_kl, g_kl);
    SYM(p_vTh, g_vTh); SYM(p_vTl, g_vTl);
    SYM(p_qh, g_qh);   SYM(p_ql, g_ql);
    SYM(p_ah, g_ah);   SYM(p_al, g_al);
    SYM(p_h1h, g_h1h); SYM(p_h1l, g_h1l);
    SYM(p_o2, g_o2);
    SYM(p_wkvTh, g_wkvTh); SYM(p_wkvTl, g_wkvTl);
    SYM(p_wqTh, g_wqTh);   SYM(p_wqTl, g_wqTl);
    SYM(p_w1Th, g_w1Th);   SYM(p_w1Tl, g_w1Tl);
    SYM(p_w2Th, g_w2Th);   SYM(p_w2Tl, g_w2Tl);

    cudaFuncSetAttribute(gemm_b3<0>, cudaFuncAttributeMaxDynamicSharedMemorySize, GSMEM);
    cudaFuncSetAttribute(gemm_b3<1>, cudaFuncAttributeMaxDynamicSharedMemorySize, GSMEM);
    cudaFuncSetAttribute(gemm_b3<2>, cudaFuncAttributeMaxDynamicSharedMemorySize, GSMEM);
    cudaFuncSetAttribute(gemm_b3<3>, cudaFuncAttributeMaxDynamicSharedMemorySize, GSMEM);
    cudaFuncSetAttribute(attn_b3, cudaFuncAttributeMaxDynamicSharedMemorySize, ATT_SMEM);

    // input / weight prep
    conv_split<<<(ROWS * DIMX) / 1024, 256>>>(x, (bf16*)p_xh, (bf16*)p_xl);
    conv_split<<<(ROWS * DIMX) / 1024, 256>>>(context, (bf16*)p_ch, (bf16*)p_cl);
    transpose_conv<<<dim3(2048 / 32, 1024 / 32), dim3(32, 8)>>>(
        w_kv, (bf16*)p_wkvTh, (bf16*)p_wkvTl, DIMX, 2 * INNER);
    transpose_conv<<<dim3(1024 / 32, 1024 / 32), dim3(32, 8)>>>(
        w_q, (bf16*)p_wqTh, (bf16*)p_wqTl, DIMX, INNER);
    transpose_conv<<<dim3(1024 / 32, 1024 / 32), dim3(32, 8)>>>(
        w_out1, (bf16*)p_w1Th, (bf16*)p_w1Tl, INNER, DIMX);
    transpose_conv<<<dim3(1024 / 32, 1024 / 32), dim3(32, 8)>>>(
        w_out2, (bf16*)p_w2Th, (bf16*)p_w2Tl, DIMX, DIMX);

    // kv = context @ w_kv  (k -> g_kh/l, v -> g_vTh/l transposed per head)
    gemm_b3<2><<<dim3(2048 / TN, ROWS / TM), 256, GSMEM>>>(
        (const bf16*)p_ch, (const bf16*)p_cl, (const bf16*)p_wkvTh, (const bf16*)p_wkvTl,
        nullptr, (bf16*)p_kh, (bf16*)p_kl, (bf16*)p_vTh, (bf16*)p_vTl, DIMX, 1024);
    // q = x @ w_q
    gemm_b3<3><<<dim3(1024 / TN, ROWS / TM), 256, GSMEM>>>(
        (const bf16*)p_xh, (const bf16*)p_xl, (const bf16*)p_wqTh, (const bf16*)p_wqTl,
        nullptr, (bf16*)p_qh, (bf16*)p_ql, nullptr, nullptr, DIMX, 1024);
    // attention
    attn_b3<<<dim3(NQ / 128, HEADS, BATCH), 256, ATT_SMEM>>>(
        (const bf16*)p_qh, (const bf16*)p_ql, (const bf16*)p_kh, (const bf16*)p_kl,
        (const bf16*)p_vTh, (const bf16*)p_vTl, (bf16*)p_ah, (bf16*)p_al);
    // h1 = relu(attn @ w_out1)
    gemm_b3<1><<<dim3(1024 / TN, ROWS / TM), 256, GSMEM>>>(
        (const bf16*)p_ah, (const bf16*)p_al, (const bf16*)p_w1Th, (const bf16*)p_w1Tl,
        nullptr, (bf16*)p_h1h, (bf16*)p_h1l, nullptr, nullptr, INNER, 1024);
    // o2 = h1 @ w_out2
    gemm_b3<0><<<dim3(1024 / TN, ROWS / TM), 256, GSMEM>>>(
        (const bf16*)p_h1h, (const bf16*)p_h1l, (const bf16*)p_w2Th, (const bf16*)p_w2Tl,
        (float*)p_o2, nullptr, nullptr, nullptr, nullptr, DIMX, 1024);
    // layernorm -> d_out
    ln_kernel<<<ROWS, 256>>>((const float*)p_o2, gamma, out);
}